// round 2
// baseline (speedup 1.0000x reference)
#include <cuda_runtime.h>
#include <math.h>

#define HEADS 6
#define NTOK  64
#define DIM   192
#define DHEAD 32
#define MAXB  4096

// Scratch (module-static device memory — allocation-free at launch time)
__device__ float g_bias16[HEADS * NTOK * NTOK];                       // 16*sigmoid(rpb)
__device__ float g_q[(size_t)MAXB * HEADS * NTOK * DHEAD];            // normalized q [b][h][n][d]
__device__ float g_k[(size_t)MAXB * HEADS * NTOK * DHEAD];            // normalized k
__device__ float g_v[(size_t)MAXB * HEADS * NTOK * DHEAD];            // v
__device__ float g_o[(size_t)MAXB * NTOK * DIM];                      // attn output (B,N,C)

// ---------------------------------------------------------------------------
// CPB: MLP(2->512->H) on 15x15 log-coords, gather to (H,64,64), 16*sigmoid.
// ---------------------------------------------------------------------------
__global__ void cpb_kernel(const float* __restrict__ w1, const float* __restrict__ b1,
                           const float* __restrict__ w2) {
    __shared__ float tbl[225 * 6];
    int t = threadIdx.x;
    if (t < 225) {
        int a = t / 15, bb = t % 15;
        float th = (float)(a - 7) * (8.0f / 7.0f);
        float tw = (float)(bb - 7) * (8.0f / 7.0f);
        th = copysignf(log2f(fabsf(th) + 1.0f) * (1.0f / 3.0f), th);
        tw = copysignf(log2f(fabsf(tw) + 1.0f) * (1.0f / 3.0f), tw);
        float acc[6] = {0.f, 0.f, 0.f, 0.f, 0.f, 0.f};
        for (int j = 0; j < 512; ++j) {
            float hv = fmaf(th, w1[2 * j], fmaf(tw, w1[2 * j + 1], b1[j]));
            hv = fmaxf(hv, 0.0f);
#pragma unroll
            for (int hh = 0; hh < 6; ++hh)
                acc[hh] = fmaf(hv, w2[hh * 512 + j], acc[hh]);
        }
#pragma unroll
        for (int hh = 0; hh < 6; ++hh) tbl[t * 6 + hh] = acc[hh];
    }
    __syncthreads();
    for (int idx = t; idx < HEADS * 4096; idx += blockDim.x) {
        int h = idx >> 12;
        int p = idx & 4095;
        int i = p >> 6, j = p & 63;
        int dh = (i >> 3) - (j >> 3) + 7;
        int dw = (i & 7) - (j & 7) + 7;
        float v = tbl[(dh * 15 + dw) * 6 + h];
        g_bias16[idx] = 16.0f / (1.0f + expf(-v));
    }
}

__device__ __forceinline__ float dot4(float4 a, float4 b, float acc) {
    acc = fmaf(a.x, b.x, acc);
    acc = fmaf(a.y, b.y, acc);
    acc = fmaf(a.z, b.z, acc);
    acc = fmaf(a.w, b.w, acc);
    return acc;
}

// ---------------------------------------------------------------------------
// qkv GEMM: per window, out[m][j] = x[m]·qkv_w[j] + bias[j], scatter to q/k/v.
// 256 threads: thread owns rows {r, r+32} x cols {jc..jc+3} of each 32-col tile.
// ---------------------------------------------------------------------------
__global__ __launch_bounds__(256, 1)
void qkv_kernel(const float* __restrict__ x, const float* __restrict__ qkvw,
                const float* __restrict__ qb, const float* __restrict__ vb) {
    extern __shared__ float sm[];
    float* xs = sm;            // 64*192
    float* ws = sm + 12288;    // 32*192
    const int b = blockIdx.x, t = threadIdx.x;

    const float* xg = x + (size_t)b * 12288;
    for (int i = t; i < 12288; i += 256) xs[i] = xg[i];
    __syncthreads();

    const int r  = t >> 3;          // 0..31
    const int jc = (t & 7) * 4;     // 0..28

    for (int J = 0; J < 576; J += 32) {
        for (int i = t; i < 6144; i += 256) ws[i] = qkvw[J * 192 + i];
        __syncthreads();

        float a0[4] = {0.f, 0.f, 0.f, 0.f};
        float a1[4] = {0.f, 0.f, 0.f, 0.f};
        const float* x0 = xs + r * 192;
        const float* x1 = xs + (r + 32) * 192;
#pragma unroll 4
        for (int c = 0; c < 192; c += 4) {
            float4 xv0 = *(const float4*)(x0 + c);
            float4 xv1 = *(const float4*)(x1 + c);
#pragma unroll
            for (int u = 0; u < 4; ++u) {
                float4 wv = *(const float4*)(ws + (jc + u) * 192 + c);
                a0[u] = dot4(xv0, wv, a0[u]);
                a1[u] = dot4(xv1, wv, a1[u]);
            }
        }
#pragma unroll
        for (int u = 0; u < 4; ++u) {
            int j  = J + jc + u;
            int s  = j / 192;
            int rr = j - s * 192;
            int h  = rr >> 5, d = rr & 31;
            float bias = (s == 0) ? qb[rr] : ((s == 2) ? vb[rr] : 0.0f);
            float* dst = (s == 0) ? g_q : ((s == 1) ? g_k : g_v);
            size_t hb = ((size_t)b * HEADS + h) * (NTOK * DHEAD);
            dst[hb + (size_t)r * 32 + d]        = a0[u] + bias;
            dst[hb + (size_t)(r + 32) * 32 + d] = a1[u] + bias;
        }
        __syncthreads();
    }
}

// ---------------------------------------------------------------------------
// L2-normalize rows of g_q and g_k (one warp per 32-float row).
// ---------------------------------------------------------------------------
__global__ void norm_kernel(int nrows) {
    int row = blockIdx.x * 8 + (threadIdx.x >> 5);
    int l = threadIdx.x & 31;
    float* buf;
    int ri;
    if (row < nrows) { buf = g_q; ri = row; }
    else             { buf = g_k; ri = row - nrows; }
    float* p = buf + (size_t)ri * 32 + l;
    float v = *p;
    float ss = v * v;
#pragma unroll
    for (int off = 16; off; off >>= 1)
        ss += __shfl_xor_sync(0xffffffffu, ss, off);
    *p = v / fmaxf(sqrtf(ss), 1e-12f);
}

// ---------------------------------------------------------------------------
// Attention per (window, head): logits -> +bias+mask -> softmax -> AV.
// ---------------------------------------------------------------------------
__global__ __launch_bounds__(256)
void attn_kernel(const float* __restrict__ mask, const float* __restrict__ ls) {
    __shared__ float qh[2048], kh[2048], vh[2048], at[64 * 65];
    const int b = blockIdx.x, h = blockIdx.y, t = threadIdx.x;

    size_t base = ((size_t)b * HEADS + h) * 2048;
    for (int i = t; i < 2048; i += 256) {
        qh[i] = g_q[base + i];
        kh[i] = g_k[base + i];
        vh[i] = g_v[base + i];
    }
    __syncthreads();

    const float scale = expf(fminf(ls[h], 4.6051702f));  // exp(min(ls, log(100)))
    const int m = t >> 2, ag = t & 3;
    const float* bh = g_bias16 + h * 4096;
    const float* mw = mask + (size_t)(b & 63) * 4096;

    // logits: thread computes at[m][ag*16 .. +16]
    float acc[16];
#pragma unroll
    for (int i = 0; i < 16; ++i) acc[i] = 0.f;
#pragma unroll
    for (int d = 0; d < 32; d += 4) {
        float4 q4 = *(const float4*)(qh + m * 32 + d);
#pragma unroll
        for (int i = 0; i < 16; ++i) {
            float4 k4 = *(const float4*)(kh + (ag * 16 + i) * 32 + d);
            acc[i] = dot4(q4, k4, acc[i]);
        }
    }
#pragma unroll
    for (int i = 0; i < 16; ++i) {
        int n = ag * 16 + i;
        at[m * 65 + n] = fmaf(acc[i], scale, bh[m * 64 + n] + mw[m * 64 + n]);
    }
    __syncthreads();

    // softmax: warp per row, lane covers cols l and 32+l
    const int w = t >> 5, l = t & 31;
    for (int row = w; row < 64; row += 8) {
        float a0 = at[row * 65 + l];
        float a1 = at[row * 65 + 32 + l];
        float mx = fmaxf(a0, a1);
#pragma unroll
        for (int off = 16; off; off >>= 1)
            mx = fmaxf(mx, __shfl_xor_sync(0xffffffffu, mx, off));
        float e0 = __expf(a0 - mx);
        float e1 = __expf(a1 - mx);
        float ssum = e0 + e1;
#pragma unroll
        for (int off = 16; off; off >>= 1)
            ssum += __shfl_xor_sync(0xffffffffu, ssum, off);
        float inv = 1.0f / ssum;
        at[row * 65 + l]      = e0 * inv;
        at[row * 65 + 32 + l] = e1 * inv;
    }
    __syncthreads();

    // AV: thread computes o[m][d0..d0+8) for this head
    float oa[8];
#pragma unroll
    for (int i = 0; i < 8; ++i) oa[i] = 0.f;
    const int d0 = ag * 8;
    for (int n = 0; n < 64; ++n) {
        float a = at[m * 65 + n];
        float4 v0 = *(const float4*)(vh + n * 32 + d0);
        float4 v1 = *(const float4*)(vh + n * 32 + d0 + 4);
        oa[0] = fmaf(a, v0.x, oa[0]); oa[1] = fmaf(a, v0.y, oa[1]);
        oa[2] = fmaf(a, v0.z, oa[2]); oa[3] = fmaf(a, v0.w, oa[3]);
        oa[4] = fmaf(a, v1.x, oa[4]); oa[5] = fmaf(a, v1.y, oa[5]);
        oa[6] = fmaf(a, v1.z, oa[6]); oa[7] = fmaf(a, v1.w, oa[7]);
    }
    float* og = g_o + ((size_t)b * 64 + m) * 192 + h * 32 + d0;
#pragma unroll
    for (int i = 0; i < 8; ++i) og[i] = oa[i];
}

// ---------------------------------------------------------------------------
// proj GEMM: out[m][j] = o[m]·proj_w[j] + pb[j]
// ---------------------------------------------------------------------------
__global__ __launch_bounds__(256, 1)
void proj_kernel(const float* __restrict__ pw, const float* __restrict__ pb,
                 float* __restrict__ out) {
    extern __shared__ float sm[];
    float* os = sm;            // 64*192
    float* ws = sm + 12288;    // 32*192
    const int b = blockIdx.x, t = threadIdx.x;

    const float* og = g_o + (size_t)b * 12288;
    for (int i = t; i < 12288; i += 256) os[i] = og[i];
    __syncthreads();

    const int r  = t >> 3;
    const int jc = (t & 7) * 4;
    float* outg = out + (size_t)b * 12288;

    for (int J = 0; J < 192; J += 32) {
        for (int i = t; i < 6144; i += 256) ws[i] = pw[J * 192 + i];
        __syncthreads();

        float a0[4] = {0.f, 0.f, 0.f, 0.f};
        float a1[4] = {0.f, 0.f, 0.f, 0.f};
        const float* x0 = os + r * 192;
        const float* x1 = os + (r + 32) * 192;
#pragma unroll 4
        for (int c = 0; c < 192; c += 4) {
            float4 xv0 = *(const float4*)(x0 + c);
            float4 xv1 = *(const float4*)(x1 + c);
#pragma unroll
            for (int u = 0; u < 4; ++u) {
                float4 wv = *(const float4*)(ws + (jc + u) * 192 + c);
                a0[u] = dot4(xv0, wv, a0[u]);
                a1[u] = dot4(xv1, wv, a1[u]);
            }
        }
#pragma unroll
        for (int u = 0; u < 4; ++u) {
            int j = J + jc + u;
            outg[r * 192 + j]        = a0[u] + pb[j];
            outg[(r + 32) * 192 + j] = a1[u] + pb[j];
        }
        __syncthreads();
    }
}

// ---------------------------------------------------------------------------
extern "C" void kernel_launch(void* const* d_in, const int* in_sizes, int n_in,
                              void* d_out, int out_size) {
    const float* x    = (const float*)d_in[0];
    const float* mask = (const float*)d_in[1];
    const float* qkvw = (const float*)d_in[2];
    const float* qb   = (const float*)d_in[3];
    const float* vb   = (const float*)d_in[4];
    const float* ls   = (const float*)d_in[5];
    const float* w1   = (const float*)d_in[6];
    const float* b1   = (const float*)d_in[7];
    const float* w2   = (const float*)d_in[8];
    const float* pw   = (const float*)d_in[9];
    const float* pb   = (const float*)d_in[10];
    float* out = (float*)d_out;

    int B = in_sizes[0] / (NTOK * DIM);

    static bool attr_done = false;
    if (!attr_done) {
        cudaFuncSetAttribute(qkv_kernel,
                             cudaFuncAttributeMaxDynamicSharedMemorySize, 73728);
        cudaFuncSetAttribute(proj_kernel,
                             cudaFuncAttributeMaxDynamicSharedMemorySize, 73728);
        attr_done = true;
    }

    cpb_kernel<<<1, 256>>>(w1, b1, w2);
    qkv_kernel<<<B, 256, 73728>>>(x, qkvw, qb, vb);
    int nrows = B * HEADS * NTOK;
    norm_kernel<<<(2 * nrows) / 8, 256>>>(nrows);
    attn_kernel<<<dim3(B, HEADS), 256>>>(mask, ls);
    proj_kernel<<<B, 256, 73728>>>(pw, pb, out);
}

// round 4
// speedup vs baseline: 4.5066x; 4.5066x over previous
#include <cuda_runtime.h>
#include <math.h>

#define HEADS 6
#define NTOK  64
#define DIM   192
#define DHEAD 32
#define MAXB  4096

// Scratch (module-static device memory — allocation-free at launch time)
__device__ float g_bias16[HEADS * NTOK * NTOK];             // 16*sigmoid(rpb)
__device__ float g_q[(size_t)MAXB * HEADS * NTOK * DHEAD];  // q [b][h][n][d] (raw)
__device__ float g_k[(size_t)MAXB * HEADS * NTOK * DHEAD];  // k
__device__ float g_v[(size_t)MAXB * HEADS * NTOK * DHEAD];  // v
__device__ float g_o[(size_t)MAXB * NTOK * DIM];            // attn output (B,N,C)

// ---------------------------------------------------------------------------
// CPB: MLP(2->512->H) on 15x15 log-coords, gather to (H,64,64), 16*sigmoid.
// ---------------------------------------------------------------------------
__global__ void cpb_kernel(const float* __restrict__ w1, const float* __restrict__ b1,
                           const float* __restrict__ w2) {
    __shared__ float tbl[225 * 6];
    int t = threadIdx.x;
    if (t < 225) {
        int a = t / 15, bb = t % 15;
        float th = (float)(a - 7) * (8.0f / 7.0f);
        float tw = (float)(bb - 7) * (8.0f / 7.0f);
        th = copysignf(log2f(fabsf(th) + 1.0f) * (1.0f / 3.0f), th);
        tw = copysignf(log2f(fabsf(tw) + 1.0f) * (1.0f / 3.0f), tw);
        float acc[6] = {0.f, 0.f, 0.f, 0.f, 0.f, 0.f};
        for (int j = 0; j < 512; ++j) {
            float hv = fmaf(th, w1[2 * j], fmaf(tw, w1[2 * j + 1], b1[j]));
            hv = fmaxf(hv, 0.0f);
#pragma unroll
            for (int hh = 0; hh < 6; ++hh)
                acc[hh] = fmaf(hv, w2[hh * 512 + j], acc[hh]);
        }
#pragma unroll
        for (int hh = 0; hh < 6; ++hh) tbl[t * 6 + hh] = acc[hh];
    }
    __syncthreads();
    for (int idx = t; idx < HEADS * 4096; idx += blockDim.x) {
        int h = idx >> 12;
        int p = idx & 4095;
        int i = p >> 6, j = p & 63;
        int dh = (i >> 3) - (j >> 3) + 7;
        int dw = (i & 7) - (j & 7) + 7;
        float v = tbl[(dh * 15 + dw) * 6 + h];
        g_bias16[idx] = 16.0f / (1.0f + expf(-v));
    }
}

// ---------------------------------------------------------------------------
// Shared GEMM core: C[64 x NCOLS] = X[64x192] @ W[NCOLS x 192]^T, tiled by 32
// cols. xs: [64][196] padded. wt: transposed tile [192][36] (conflict-free).
// Thread t: rows m0=2*(t>>3), m1=m0+1; cols jc=(t&7)*4 .. +4.
// ---------------------------------------------------------------------------
#define XS_STRIDE 196
#define WT_STRIDE 36
#define GEMM_SMEM_FLOATS (64 * XS_STRIDE + 192 * WT_STRIDE)
#define GEMM_SMEM_BYTES  (GEMM_SMEM_FLOATS * 4)   // 77824 B

__device__ __forceinline__ void gemm_tile_compute(const float* xs, const float* wt,
                                                  int m0, int m1, int jc,
                                                  float* acc0, float* acc1) {
#pragma unroll
    for (int u = 0; u < 4; ++u) { acc0[u] = 0.f; acc1[u] = 0.f; }
    const float* x0 = xs + m0 * XS_STRIDE;
    const float* x1 = xs + m1 * XS_STRIDE;
#pragma unroll 4
    for (int c = 0; c < 192; c += 4) {
        float4 xa = *(const float4*)(x0 + c);
        float4 xb = *(const float4*)(x1 + c);
        float4 w0 = *(const float4*)(wt + (c + 0) * WT_STRIDE + jc);
        float4 w1 = *(const float4*)(wt + (c + 1) * WT_STRIDE + jc);
        float4 w2 = *(const float4*)(wt + (c + 2) * WT_STRIDE + jc);
        float4 w3 = *(const float4*)(wt + (c + 3) * WT_STRIDE + jc);
        acc0[0] = fmaf(xa.x, w0.x, acc0[0]); acc1[0] = fmaf(xb.x, w0.x, acc1[0]);
        acc0[1] = fmaf(xa.x, w0.y, acc0[1]); acc1[1] = fmaf(xb.x, w0.y, acc1[1]);
        acc0[2] = fmaf(xa.x, w0.z, acc0[2]); acc1[2] = fmaf(xb.x, w0.z, acc1[2]);
        acc0[3] = fmaf(xa.x, w0.w, acc0[3]); acc1[3] = fmaf(xb.x, w0.w, acc1[3]);
        acc0[0] = fmaf(xa.y, w1.x, acc0[0]); acc1[0] = fmaf(xb.y, w1.x, acc1[0]);
        acc0[1] = fmaf(xa.y, w1.y, acc0[1]); acc1[1] = fmaf(xb.y, w1.y, acc1[1]);
        acc0[2] = fmaf(xa.y, w1.z, acc0[2]); acc1[2] = fmaf(xb.y, w1.z, acc1[2]);
        acc0[3] = fmaf(xa.y, w1.w, acc0[3]); acc1[3] = fmaf(xb.y, w1.w, acc1[3]);
        acc0[0] = fmaf(xa.z, w2.x, acc0[0]); acc1[0] = fmaf(xb.z, w2.x, acc1[0]);
        acc0[1] = fmaf(xa.z, w2.y, acc0[1]); acc1[1] = fmaf(xb.z, w2.y, acc1[1]);
        acc0[2] = fmaf(xa.z, w2.z, acc0[2]); acc1[2] = fmaf(xb.z, w2.z, acc1[2]);
        acc0[3] = fmaf(xa.z, w2.w, acc0[3]); acc1[3] = fmaf(xb.z, w2.w, acc1[3]);
        acc0[0] = fmaf(xa.w, w3.x, acc0[0]); acc1[0] = fmaf(xb.w, w3.x, acc1[0]);
        acc0[1] = fmaf(xa.w, w3.y, acc0[1]); acc1[1] = fmaf(xb.w, w3.y, acc1[1]);
        acc0[2] = fmaf(xa.w, w3.z, acc0[2]); acc1[2] = fmaf(xb.w, w3.z, acc1[2]);
        acc0[3] = fmaf(xa.w, w3.w, acc0[3]); acc1[3] = fmaf(xb.w, w3.w, acc1[3]);
    }
}

__device__ __forceinline__ void stage_wt(float* wt, const float* __restrict__ wrow,
                                         int t) {
    // wrow points at W[J][0]; load 32x192 floats coalesced, store transposed.
    const float4* src = (const float4*)wrow;
    for (int i = t; i < 1536; i += 256) {
        float4 v = src[i];
        int idx = i * 4;
        int j = idx / 192, c = idx % 192;
        wt[(c + 0) * WT_STRIDE + j] = v.x;
        wt[(c + 1) * WT_STRIDE + j] = v.y;
        wt[(c + 2) * WT_STRIDE + j] = v.z;
        wt[(c + 3) * WT_STRIDE + j] = v.w;
    }
}

// ---------------------------------------------------------------------------
// qkv GEMM: per window, scatter into g_q/g_k/g_v [b][h][n][d] with bias.
// ---------------------------------------------------------------------------
__global__ __launch_bounds__(256, 1)
void qkv_kernel(const float* __restrict__ x, const float* __restrict__ qkvw,
                const float* __restrict__ qb, const float* __restrict__ vb) {
    extern __shared__ float sm[];
    float* xs = sm;
    float* wt = sm + 64 * XS_STRIDE;
    const int b = blockIdx.x, t = threadIdx.x;

    const float4* xg = (const float4*)(x + (size_t)b * 12288);
    for (int i = t; i < 3072; i += 256) {
        float4 v = xg[i];
        int idx = i * 4;
        int n = idx / 192, c = idx % 192;
        *(float4*)(xs + n * XS_STRIDE + c) = v;
    }
    __syncthreads();

    const int rt = t >> 3;
    const int m0 = rt * 2, m1 = m0 + 1;
    const int jc = (t & 7) * 4;

    for (int J = 0; J < 576; J += 32) {
        stage_wt(wt, qkvw + (size_t)J * 192, t);
        __syncthreads();

        float acc0[4], acc1[4];
        gemm_tile_compute(xs, wt, m0, m1, jc, acc0, acc1);

        const int s = J / 192;
        const int hh = (J % 192) >> 5;          // head for this tile
        float* dst = (s == 0) ? g_q : ((s == 1) ? g_k : g_v);
        size_t hb = ((size_t)b * HEADS + hh) * (NTOK * DHEAD);
        float4 bv = make_float4(0.f, 0.f, 0.f, 0.f);
        if (s == 0) bv = *(const float4*)(qb + hh * 32 + jc);
        else if (s == 2) bv = *(const float4*)(vb + hh * 32 + jc);
        float4 r0 = make_float4(acc0[0] + bv.x, acc0[1] + bv.y, acc0[2] + bv.z, acc0[3] + bv.w);
        float4 r1 = make_float4(acc1[0] + bv.x, acc1[1] + bv.y, acc1[2] + bv.z, acc1[3] + bv.w);
        *(float4*)(dst + hb + (size_t)m0 * 32 + jc) = r0;
        *(float4*)(dst + hb + (size_t)m1 * 32 + jc) = r1;
        __syncthreads();
    }
}

// ---------------------------------------------------------------------------
// Attention per (window, head): normalize q,k (scale folded into q) ->
// logits + bias + mask -> softmax -> AV. Conflict-free smem (stride 36).
// ---------------------------------------------------------------------------
#define QK_STRIDE 36
__global__ __launch_bounds__(256)
void attn_kernel(const float* __restrict__ mask, const float* __restrict__ ls) {
    __shared__ float qh[64 * QK_STRIDE], kh[64 * QK_STRIDE], vh[64 * QK_STRIDE];
    __shared__ float at[64 * 65];
    const int b = blockIdx.x, h = blockIdx.y, t = threadIdx.x;
    const int w = t >> 5, l = t & 31;

    size_t base = ((size_t)b * HEADS + h) * 2048;
    for (int i = t; i < 512; i += 256) {
        float4 q4 = *(const float4*)(g_q + base + i * 4);
        float4 k4 = *(const float4*)(g_k + base + i * 4);
        float4 v4 = *(const float4*)(g_v + base + i * 4);
        int idx = i * 4;
        int n = idx >> 5, d = idx & 31;
        *(float4*)(qh + n * QK_STRIDE + d) = q4;
        *(float4*)(kh + n * QK_STRIDE + d) = k4;
        *(float4*)(vh + n * QK_STRIDE + d) = v4;
    }
    // stage bias + mask into attn scratch (coalesced gmem reads)
    const float* bh = g_bias16 + h * 4096;
    const float* mw = mask + (size_t)(b & 63) * 4096;
    for (int idx = t; idx < 4096; idx += 256) {
        int i = idx >> 6, j = idx & 63;
        at[i * 65 + j] = bh[idx] + mw[idx];
    }
    __syncthreads();

    // normalize q (with scale) and k rows: warp per row, lane = d
    const float scale = expf(fminf(ls[h], 4.6051702f));
    for (int r = w; r < 128; r += 8) {
        float* p = (r < 64) ? (qh + r * QK_STRIDE + l) : (kh + (r - 64) * QK_STRIDE + l);
        float v = *p;
        float ss = v * v;
#pragma unroll
        for (int off = 16; off; off >>= 1)
            ss += __shfl_xor_sync(0xffffffffu, ss, off);
        float inv = 1.0f / fmaxf(sqrtf(ss), 1e-12f);
        if (r < 64) inv *= scale;
        *p = v * inv;
    }
    __syncthreads();

    // logits: thread (ag = t>>6, m = t&63) computes at[m][ag*16 .. +16]
    const int ag = t >> 6, m = t & 63;
    {
        float acc[16];
#pragma unroll
        for (int i = 0; i < 16; ++i) acc[i] = 0.f;
#pragma unroll
        for (int d = 0; d < 32; d += 4) {
            float4 q4 = *(const float4*)(qh + m * QK_STRIDE + d);
#pragma unroll
            for (int i = 0; i < 16; ++i) {
                float4 k4 = *(const float4*)(kh + (ag * 16 + i) * QK_STRIDE + d);
                acc[i] = fmaf(q4.x, k4.x, acc[i]);
                acc[i] = fmaf(q4.y, k4.y, acc[i]);
                acc[i] = fmaf(q4.z, k4.z, acc[i]);
                acc[i] = fmaf(q4.w, k4.w, acc[i]);
            }
        }
#pragma unroll
        for (int i = 0; i < 16; ++i) {
            int n = ag * 16 + i;
            at[m * 65 + n] += acc[i];
        }
    }
    __syncthreads();

    // softmax: warp per row, lane covers cols l and 32+l
    for (int row = w; row < 64; row += 8) {
        float a0 = at[row * 65 + l];
        float a1 = at[row * 65 + 32 + l];
        float mx = fmaxf(a0, a1);
#pragma unroll
        for (int off = 16; off; off >>= 1)
            mx = fmaxf(mx, __shfl_xor_sync(0xffffffffu, mx, off));
        float e0 = __expf(a0 - mx);
        float e1 = __expf(a1 - mx);
        float ssum = e0 + e1;
#pragma unroll
        for (int off = 16; off; off >>= 1)
            ssum += __shfl_xor_sync(0xffffffffu, ssum, off);
        float inv = 1.0f / ssum;
        at[row * 65 + l]      = e0 * inv;
        at[row * 65 + 32 + l] = e1 * inv;
    }
    __syncthreads();

    // AV: thread computes o[m][d0..d0+8)
    float oa[8];
#pragma unroll
    for (int i = 0; i < 8; ++i) oa[i] = 0.f;
    const int d0 = ag * 8;
    for (int n = 0; n < 64; ++n) {
        float a = at[m * 65 + n];
        float4 v0 = *(const float4*)(vh + n * QK_STRIDE + d0);
        float4 v1 = *(const float4*)(vh + n * QK_STRIDE + d0 + 4);
        oa[0] = fmaf(a, v0.x, oa[0]); oa[1] = fmaf(a, v0.y, oa[1]);
        oa[2] = fmaf(a, v0.z, oa[2]); oa[3] = fmaf(a, v0.w, oa[3]);
        oa[4] = fmaf(a, v1.x, oa[4]); oa[5] = fmaf(a, v1.y, oa[5]);
        oa[6] = fmaf(a, v1.z, oa[6]); oa[7] = fmaf(a, v1.w, oa[7]);
    }
    float* og = g_o + ((size_t)b * 64 + m) * 192 + h * 32 + d0;
    *(float4*)og       = make_float4(oa[0], oa[1], oa[2], oa[3]);
    *(float4*)(og + 4) = make_float4(oa[4], oa[5], oa[6], oa[7]);
}

// ---------------------------------------------------------------------------
// proj GEMM: out[m][j] = o[m]·proj_w[j] + pb[j]
// ---------------------------------------------------------------------------
__global__ __launch_bounds__(256, 1)
void proj_kernel(const float* __restrict__ pw, const float* __restrict__ pb,
                 float* __restrict__ out) {
    extern __shared__ float sm[];
    float* xs = sm;
    float* wt = sm + 64 * XS_STRIDE;
    const int b = blockIdx.x, t = threadIdx.x;

    const float4* og = (const float4*)(g_o + (size_t)b * 12288);
    for (int i = t; i < 3072; i += 256) {
        float4 v = og[i];
        int idx = i * 4;
        int n = idx / 192, c = idx % 192;
        *(float4*)(xs + n * XS_STRIDE + c) = v;
    }
    __syncthreads();

    const int rt = t >> 3;
    const int m0 = rt * 2, m1 = m0 + 1;
    const int jc = (t & 7) * 4;
    float* outg = out + (size_t)b * 12288;

    for (int J = 0; J < 192; J += 32) {
        stage_wt(wt, pw + (size_t)J * 192, t);
        __syncthreads();

        float acc0[4], acc1[4];
        gemm_tile_compute(xs, wt, m0, m1, jc, acc0, acc1);

        float4 bv = *(const float4*)(pb + J + jc);
        float4 r0 = make_float4(acc0[0] + bv.x, acc0[1] + bv.y, acc0[2] + bv.z, acc0[3] + bv.w);
        float4 r1 = make_float4(acc1[0] + bv.x, acc1[1] + bv.y, acc1[2] + bv.z, acc1[3] + bv.w);
        *(float4*)(outg + m0 * 192 + J + jc) = r0;
        *(float4*)(outg + m1 * 192 + J + jc) = r1;
        __syncthreads();
    }
}

// ---------------------------------------------------------------------------
extern "C" void kernel_launch(void* const* d_in, const int* in_sizes, int n_in,
                              void* d_out, int out_size) {
    const float* x    = (const float*)d_in[0];
    const float* mask = (const float*)d_in[1];
    const float* qkvw = (const float*)d_in[2];
    const float* qb   = (const float*)d_in[3];
    const float* vb   = (const float*)d_in[4];
    const float* ls   = (const float*)d_in[5];
    const float* w1   = (const float*)d_in[6];
    const float* b1   = (const float*)d_in[7];
    const float* w2   = (const float*)d_in[8];
    const float* pw   = (const float*)d_in[9];
    const float* pb   = (const float*)d_in[10];
    float* out = (float*)d_out;

    int B = in_sizes[0] / (NTOK * DIM);

    cudaFuncSetAttribute(qkv_kernel,
                         cudaFuncAttributeMaxDynamicSharedMemorySize, GEMM_SMEM_BYTES);
    cudaFuncSetAttribute(proj_kernel,
                         cudaFuncAttributeMaxDynamicSharedMemorySize, GEMM_SMEM_BYTES);

    cpb_kernel<<<1, 256>>>(w1, b1, w2);
    qkv_kernel<<<B, 256, GEMM_SMEM_BYTES>>>(x, qkvw, qb, vb);
    attn_kernel<<<dim3(B, HEADS), 256>>>(mask, ls);
    proj_kernel<<<B, 256, GEMM_SMEM_BYTES>>>(pw, pb, out);
}

// round 7
// speedup vs baseline: 11.3676x; 2.5224x over previous
#include <cuda_runtime.h>
#include <cuda_bf16.h>
#include <math.h>
#include <stdint.h>

#define HEADS 6
#define NTOK  64
#define DIM   192
#define MAXB  4096

// ---------------- device scratch ----------------
__device__ float g_bias16[HEADS * NTOK * NTOK];
__device__ float g_q[(size_t)MAXB * HEADS * NTOK * 32];
__device__ float g_k[(size_t)MAXB * HEADS * NTOK * 32];
__device__ float g_v[(size_t)MAXB * HEADS * NTOK * 32];
__device__ float g_o[(size_t)MAXB * NTOK * DIM];
__device__ __align__(16) __nv_bfloat16 gwq_hi[576 * 192];
__device__ __align__(16) __nv_bfloat16 gwq_lo[576 * 192];
__device__ __align__(16) __nv_bfloat16 gwp_hi[192 * 192];
__device__ __align__(16) __nv_bfloat16 gwp_lo[192 * 192];

// ---------------- arch-generic PTX helpers (compute_103-safe) ----------------
__device__ __forceinline__ uint32_t smem_u32(const void* p) {
    uint32_t a;
    asm("{ .reg .u64 t; cvta.to.shared.u64 t, %1; cvt.u32.u64 %0, t; }" : "=r"(a) : "l"(p));
    return a;
}
__device__ __forceinline__ void cp_async16(uint32_t saddr, const void* gptr) {
    asm volatile("cp.async.cg.shared.global [%0], [%1], 16;" :: "r"(saddr), "l"(gptr)
                 : "memory");
}
__device__ __forceinline__ void cp_commit() {
    asm volatile("cp.async.commit_group;" ::: "memory");
}
__device__ __forceinline__ void cp_wait0() {
    asm volatile("cp.async.wait_group 0;" ::: "memory");
}
__device__ __forceinline__ void ldsm4(uint32_t* r, uint32_t addr) {
    asm volatile("ldmatrix.sync.aligned.m8n8.x4.shared.b16 {%0,%1,%2,%3}, [%4];"
                 : "=r"(r[0]), "=r"(r[1]), "=r"(r[2]), "=r"(r[3]) : "r"(addr));
}
__device__ __forceinline__ void mma16816(float* c, const uint32_t* a, const uint32_t* b) {
    asm volatile(
        "mma.sync.aligned.m16n8k16.row.col.f32.bf16.bf16.f32 "
        "{%0,%1,%2,%3}, {%4,%5,%6,%7}, {%8,%9}, {%0,%1,%2,%3};"
        : "+f"(c[0]), "+f"(c[1]), "+f"(c[2]), "+f"(c[3])
        : "r"(a[0]), "r"(a[1]), "r"(a[2]), "r"(a[3]), "r"(b[0]), "r"(b[1]));
}
__device__ __forceinline__ uint32_t pk(__nv_bfloat16 a, __nv_bfloat16 b) {
    __nv_bfloat162 t = __halves2bfloat162(a, b);
    return *(uint32_t*)&t;
}

// smem layout (bytes). Row stride 400 B (= 25 x 16B, step-4-bank rows: LDSM conflict-free)
#define ASTRIDE 400
#define A_HI    0
#define A_LO    51200
#define BBUF(buf)       (102400 + (buf) * 51200)   // hi at +0, lo at +25600
#define SBIAS   204800
#define SM_DYN  (204800 + 2304)

// ---------------------------------------------------------------------------
// weight prep: split fp32 weights into bf16 hi/lo
// ---------------------------------------------------------------------------
__global__ void prep_w_kernel(const float* __restrict__ qkvw, const float* __restrict__ pw) {
    const int n1 = 576 * 192, n2 = 192 * 192;
    for (int i = blockIdx.x * blockDim.x + threadIdx.x; i < n1 + n2;
         i += gridDim.x * blockDim.x) {
        float v = (i < n1) ? qkvw[i] : pw[i - n1];
        __nv_bfloat16 h = __float2bfloat16(v);
        __nv_bfloat16 l = __float2bfloat16(v - __bfloat162float(h));
        if (i < n1) { gwq_hi[i] = h; gwq_lo[i] = l; }
        else        { gwp_hi[i - n1] = h; gwp_lo[i - n1] = l; }
    }
}

// ---------------------------------------------------------------------------
// stage A (fp32 -> bf16 hi/lo) into smem, 128 rows x 192 cols
// ---------------------------------------------------------------------------
__device__ __forceinline__ void stage_A(char* sm, const float* __restrict__ A, int t) {
    const float4* src = (const float4*)A;
#pragma unroll 4
    for (int i = t; i < 6144; i += 256) {
        float4 v = src[i];
        int row = i / 48, c4 = (i - row * 48) * 4;
        __nv_bfloat16 hx = __float2bfloat16(v.x), hy = __float2bfloat16(v.y);
        __nv_bfloat16 hz = __float2bfloat16(v.z), hw = __float2bfloat16(v.w);
        __nv_bfloat16 lx = __float2bfloat16(v.x - __bfloat162float(hx));
        __nv_bfloat16 ly = __float2bfloat16(v.y - __bfloat162float(hy));
        __nv_bfloat16 lz = __float2bfloat16(v.z - __bfloat162float(hz));
        __nv_bfloat16 lw = __float2bfloat16(v.w - __bfloat162float(hw));
        uint32_t off = row * ASTRIDE + c4 * 2;
        *(uint2*)(sm + A_HI + off) = make_uint2(pk(hx, hy), pk(hz, hw));
        *(uint2*)(sm + A_LO + off) = make_uint2(pk(lx, ly), pk(lz, lw));
    }
}

// stage one 64-row B chunk (hi+lo) via cp.async into buffer `buf`
__device__ __forceinline__ void stage_B_async(uint32_t smb, int buf,
                                              const __nv_bfloat16* __restrict__ Whi,
                                              const __nv_bfloat16* __restrict__ Wlo,
                                              int J, int t) {
    uint32_t bh = smb + BBUF(buf), bl = bh + 25600;
#pragma unroll
    for (int i = t; i < 1536; i += 256) {
        int n = i / 24, c = (i - n * 24) * 16;          // c = byte offset in row
        uint32_t so = n * ASTRIDE + c;
        cp_async16(bh + so, (const char*)(Whi + (size_t)(J + n) * 192) + c);
        cp_async16(bl + so, (const char*)(Wlo + (size_t)(J + n) * 192) + c);
    }
    cp_commit();
}

// ---------------------------------------------------------------------------
// Warp-MMA GEMM body: computes C[128 x 64] chunk, 3-term bf16 split.
// warp_m = warp&3 (rows warp_m*32), warp_n = warp>>2 (cols warp_n*32).
// acc[mh][tn][4]: mh = m-half(16), tn = n8 tile (0..3).
// ---------------------------------------------------------------------------
__device__ __forceinline__ void mma_chunk(uint32_t smb, int buf, int warp, int lane,
                                          float acc[2][4][4]) {
    const int warp_m = warp & 3, warp_n = warp >> 2;
    const uint32_t lrow = lane & 15;
    const uint32_t lcol = (lane >> 4) * 16;
    const uint32_t a_hi = smb + A_HI + (warp_m * 32 + lrow) * ASTRIDE + lcol;
    const uint32_t a_lo = a_hi + (A_LO - A_HI);
    const uint32_t b_hi = smb + BBUF(buf) + (warp_n * 32 + lrow) * ASTRIDE + lcol;
    const uint32_t b_lo = b_hi + 25600;

#pragma unroll
    for (int ks = 0; ks < 12; ++ks) {
        uint32_t ah[2][4], al[2][4], bh[2][4], bl[2][4];
#pragma unroll
        for (int mh = 0; mh < 2; ++mh) {
            ldsm4(ah[mh], a_hi + mh * 16 * ASTRIDE + ks * 32);
            ldsm4(al[mh], a_lo + mh * 16 * ASTRIDE + ks * 32);
        }
#pragma unroll
        for (int nh = 0; nh < 2; ++nh) {
            ldsm4(bh[nh], b_hi + nh * 16 * ASTRIDE + ks * 32);
            ldsm4(bl[nh], b_lo + nh * 16 * ASTRIDE + ks * 32);
        }
#pragma unroll
        for (int mh = 0; mh < 2; ++mh)
#pragma unroll
            for (int nh = 0; nh < 2; ++nh) {
                uint32_t b0h[2] = {bh[nh][0], bh[nh][2]};
                uint32_t b1h[2] = {bh[nh][1], bh[nh][3]};
                uint32_t b0l[2] = {bl[nh][0], bl[nh][2]};
                uint32_t b1l[2] = {bl[nh][1], bl[nh][3]};
                mma16816(acc[mh][nh * 2 + 0], ah[mh], b0h);
                mma16816(acc[mh][nh * 2 + 0], ah[mh], b0l);
                mma16816(acc[mh][nh * 2 + 0], al[mh], b0h);
                mma16816(acc[mh][nh * 2 + 1], ah[mh], b1h);
                mma16816(acc[mh][nh * 2 + 1], ah[mh], b1l);
                mma16816(acc[mh][nh * 2 + 1], al[mh], b1h);
            }
    }
}

// ---------------------------------------------------------------------------
// qkv GEMM: CTA = 2 windows (M=128), 9 N-chunks of 64 over 576 cols.
// ---------------------------------------------------------------------------
__global__ __launch_bounds__(256, 1)
void qkv_mma_kernel(const float* __restrict__ x, const float* __restrict__ qb,
                    const float* __restrict__ vb) {
    extern __shared__ char sm[];
    const uint32_t smb = smem_u32(sm);
    const int t = threadIdx.x, warp = t >> 5, lane = t & 31;

    float* sbias = (float*)(sm + SBIAS);
    for (int i = t; i < 576; i += 256) {
        int s = i / 192, r = i - s * 192;
        sbias[i] = (s == 0) ? qb[r] : ((s == 2) ? vb[r] : 0.0f);
    }
    stage_A(sm, x + (size_t)blockIdx.x * 24576, t);
    stage_B_async(smb, 0, gwq_hi, gwq_lo, 0, t);

    const int warp_m = warp & 3, warp_n = warp >> 2;

    for (int j = 0; j < 9; ++j) {
        cp_wait0();
        __syncthreads();
        if (j < 8) stage_B_async(smb, (j + 1) & 1, gwq_hi, gwq_lo, (j + 1) * 64, t);

        float acc[2][4][4];
#pragma unroll
        for (int a = 0; a < 2; ++a)
#pragma unroll
            for (int b2 = 0; b2 < 4; ++b2)
#pragma unroll
                for (int c = 0; c < 4; ++c) acc[a][b2][c] = 0.f;

        mma_chunk(smb, j & 1, warp, lane, acc);

        // epilogue: scatter to g_q/g_k/g_v with bias
#pragma unroll
        for (int mh = 0; mh < 2; ++mh) {
            int rowA = warp_m * 32 + mh * 16 + (lane >> 2);
            int winoff = rowA >> 6, token = rowA & 63;
#pragma unroll
            for (int tn = 0; tn < 4; ++tn) {
                int jj = j * 64 + warp_n * 32 + tn * 8 + (lane & 3) * 2;
                int s = jj / 192, rr = jj - s * 192;
                int h = rr >> 5, d = rr & 31;
                float* dst = (s == 0) ? g_q : ((s == 1) ? g_k : g_v);
                float b0 = sbias[jj], b1 = sbias[jj + 1];
                size_t base = ((((size_t)blockIdx.x * 2 + winoff) * HEADS + h) * 64) * 32;
                *(float2*)(dst + base + (size_t)token * 32 + d) =
                    make_float2(acc[mh][tn][0] + b0, acc[mh][tn][1] + b1);
                *(float2*)(dst + base + (size_t)(token + 8) * 32 + d) =
                    make_float2(acc[mh][tn][2] + b0, acc[mh][tn][3] + b1);
            }
        }
        __syncthreads();
    }
}

// ---------------------------------------------------------------------------
// proj GEMM: CTA = 2 windows, 3 N-chunks of 64 over 192 cols.
// ---------------------------------------------------------------------------
__global__ __launch_bounds__(256, 1)
void proj_mma_kernel(const float* __restrict__ pb, float* __restrict__ out) {
    extern __shared__ char sm[];
    const uint32_t smb = smem_u32(sm);
    const int t = threadIdx.x, warp = t >> 5, lane = t & 31;

    float* sbias = (float*)(sm + SBIAS);
    for (int i = t; i < 192; i += 256) sbias[i] = pb[i];
    stage_A(sm, g_o + (size_t)blockIdx.x * 24576, t);
    stage_B_async(smb, 0, gwp_hi, gwp_lo, 0, t);

    const int warp_m = warp & 3, warp_n = warp >> 2;
    float* outg = out + (size_t)blockIdx.x * 24576;

    for (int j = 0; j < 3; ++j) {
        cp_wait0();
        __syncthreads();
        if (j < 2) stage_B_async(smb, (j + 1) & 1, gwp_hi, gwp_lo, (j + 1) * 64, t);

        float acc[2][4][4];
#pragma unroll
        for (int a = 0; a < 2; ++a)
#pragma unroll
            for (int b2 = 0; b2 < 4; ++b2)
#pragma unroll
                for (int c = 0; c < 4; ++c) acc[a][b2][c] = 0.f;

        mma_chunk(smb, j & 1, warp, lane, acc);

#pragma unroll
        for (int mh = 0; mh < 2; ++mh) {
            int rowA = warp_m * 32 + mh * 16 + (lane >> 2);
#pragma unroll
            for (int tn = 0; tn < 4; ++tn) {
                int jj = j * 64 + warp_n * 32 + tn * 8 + (lane & 3) * 2;
                float b0 = sbias[jj], b1 = sbias[jj + 1];
                *(float2*)(outg + (size_t)rowA * 192 + jj) =
                    make_float2(acc[mh][tn][0] + b0, acc[mh][tn][1] + b1);
                *(float2*)(outg + (size_t)(rowA + 8) * 192 + jj) =
                    make_float2(acc[mh][tn][2] + b0, acc[mh][tn][3] + b1);
            }
        }
        __syncthreads();
    }
}

// ---------------------------------------------------------------------------
// CPB precompute (unchanged)
// ---------------------------------------------------------------------------
__global__ void cpb_kernel(const float* __restrict__ w1, const float* __restrict__ b1,
                           const float* __restrict__ w2) {
    __shared__ float tbl[225 * 6];
    int t = threadIdx.x;
    if (t < 225) {
        int a = t / 15, bb = t % 15;
        float th = (float)(a - 7) * (8.0f / 7.0f);
        float tw = (float)(bb - 7) * (8.0f / 7.0f);
        th = copysignf(log2f(fabsf(th) + 1.0f) * (1.0f / 3.0f), th);
        tw = copysignf(log2f(fabsf(tw) + 1.0f) * (1.0f / 3.0f), tw);
        float acc[6] = {0.f, 0.f, 0.f, 0.f, 0.f, 0.f};
        for (int j = 0; j < 512; ++j) {
            float hv = fmaf(th, w1[2 * j], fmaf(tw, w1[2 * j + 1], b1[j]));
            hv = fmaxf(hv, 0.0f);
#pragma unroll
            for (int hh = 0; hh < 6; ++hh)
                acc[hh] = fmaf(hv, w2[hh * 512 + j], acc[hh]);
        }
#pragma unroll
        for (int hh = 0; hh < 6; ++hh) tbl[t * 6 + hh] = acc[hh];
    }
    __syncthreads();
    for (int idx = t; idx < HEADS * 4096; idx += blockDim.x) {
        int h = idx >> 12;
        int p = idx & 4095;
        int i = p >> 6, j = p & 63;
        int dh = (i >> 3) - (j >> 3) + 7;
        int dw = (i & 7) - (j & 7) + 7;
        float v = tbl[(dh * 15 + dw) * 6 + h];
        g_bias16[idx] = 16.0f / (1.0f + expf(-v));
    }
}

// ---------------------------------------------------------------------------
// Attention (unchanged — fp32 SIMT, conflict-free smem)
// ---------------------------------------------------------------------------
#define QK_STRIDE 36
__global__ __launch_bounds__(256)
void attn_kernel(const float* __restrict__ mask, const float* __restrict__ ls) {
    __shared__ float qh[64 * QK_STRIDE], kh[64 * QK_STRIDE], vh[64 * QK_STRIDE];
    __shared__ float at[64 * 65];
    const int b = blockIdx.x, h = blockIdx.y, t = threadIdx.x;
    const int w = t >> 5, l = t & 31;

    size_t base = ((size_t)b * HEADS + h) * 2048;
    for (int i = t; i < 512; i += 256) {
        float4 q4 = *(const float4*)(g_q + base + i * 4);
        float4 k4 = *(const float4*)(g_k + base + i * 4);
        float4 v4 = *(const float4*)(g_v + base + i * 4);
        int idx = i * 4;
        int n = idx >> 5, d = idx & 31;
        *(float4*)(qh + n * QK_STRIDE + d) = q4;
        *(float4*)(kh + n * QK_STRIDE + d) = k4;
        *(float4*)(vh + n * QK_STRIDE + d) = v4;
    }
    const float* bh = g_bias16 + h * 4096;
    const float* mw = mask + (size_t)(b & 63) * 4096;
    for (int idx = t; idx < 4096; idx += 256) {
        int i = idx >> 6, j = idx & 63;
        at[i * 65 + j] = bh[idx] + mw[idx];
    }
    __syncthreads();

    const float scale = expf(fminf(ls[h], 4.6051702f));
    for (int r = w; r < 128; r += 8) {
        float* p = (r < 64) ? (qh + r * QK_STRIDE + l) : (kh + (r - 64) * QK_STRIDE + l);
        float v = *p;
        float ss = v * v;
#pragma unroll
        for (int off = 16; off; off >>= 1)
            ss += __shfl_xor_sync(0xffffffffu, ss, off);
        float inv = 1.0f / fmaxf(sqrtf(ss), 1e-12f);
        if (r < 64) inv *= scale;
        *p = v * inv;
    }
    __syncthreads();

    const int ag = t >> 6, m = t & 63;
    {
        float acc[16];
#pragma unroll
        for (int i = 0; i < 16; ++i) acc[i] = 0.f;
#pragma unroll
        for (int d = 0; d < 32; d += 4) {
            float4 q4 = *(const float4*)(qh + m * QK_STRIDE + d);
#pragma unroll
            for (int i = 0; i < 16; ++i) {
                float4 k4 = *(const float4*)(kh + (ag * 16 + i) * QK_STRIDE + d);
                acc[i] = fmaf(q4.x, k4.x, acc[i]);
                acc[i] = fmaf(q4.y, k4.y, acc[i]);
                acc[i] = fmaf(q4.z, k4.z, acc[i]);
                acc[i] = fmaf(q4.w, k4.w, acc[i]);
            }
        }
#pragma unroll
        for (int i = 0; i < 16; ++i) {
            int n = ag * 16 + i;
            at[m * 65 + n] += acc[i];
        }
    }
    __syncthreads();

    for (int row = w; row < 64; row += 8) {
        float a0 = at[row * 65 + l];
        float a1 = at[row * 65 + 32 + l];
        float mx = fmaxf(a0, a1);
#pragma unroll
        for (int off = 16; off; off >>= 1)
            mx = fmaxf(mx, __shfl_xor_sync(0xffffffffu, mx, off));
        float e0 = __expf(a0 - mx);
        float e1 = __expf(a1 - mx);
        float ssum = e0 + e1;
#pragma unroll
        for (int off = 16; off; off >>= 1)
            ssum += __shfl_xor_sync(0xffffffffu, ssum, off);
        float inv = 1.0f / ssum;
        at[row * 65 + l]      = e0 * inv;
        at[row * 65 + 32 + l] = e1 * inv;
    }
    __syncthreads();

    float oa[8];
#pragma unroll
    for (int i = 0; i < 8; ++i) oa[i] = 0.f;
    const int d0 = ag * 8;
    for (int n = 0; n < 64; ++n) {
        float a = at[m * 65 + n];
        float4 v0 = *(const float4*)(vh + n * QK_STRIDE + d0);
        float4 v1 = *(const float4*)(vh + n * QK_STRIDE + d0 + 4);
        oa[0] = fmaf(a, v0.x, oa[0]); oa[1] = fmaf(a, v0.y, oa[1]);
        oa[2] = fmaf(a, v0.z, oa[2]); oa[3] = fmaf(a, v0.w, oa[3]);
        oa[4] = fmaf(a, v1.x, oa[4]); oa[5] = fmaf(a, v1.y, oa[5]);
        oa[6] = fmaf(a, v1.z, oa[6]); oa[7] = fmaf(a, v1.w, oa[7]);
    }
    float* og = g_o + ((size_t)b * 64 + m) * 192 + h * 32 + d0;
    *(float4*)og       = make_float4(oa[0], oa[1], oa[2], oa[3]);
    *(float4*)(og + 4) = make_float4(oa[4], oa[5], oa[6], oa[7]);
}

// ---------------------------------------------------------------------------
extern "C" void kernel_launch(void* const* d_in, const int* in_sizes, int n_in,
                              void* d_out, int out_size) {
    const float* x    = (const float*)d_in[0];
    const float* mask = (const float*)d_in[1];
    const float* qkvw = (const float*)d_in[2];
    const float* qb   = (const float*)d_in[3];
    const float* vb   = (const float*)d_in[4];
    const float* ls   = (const float*)d_in[5];
    const float* w1   = (const float*)d_in[6];
    const float* b1   = (const float*)d_in[7];
    const float* w2   = (const float*)d_in[8];
    const float* pw   = (const float*)d_in[9];
    const float* pb   = (const float*)d_in[10];
    float* out = (float*)d_out;

    int B = in_sizes[0] / (NTOK * DIM);

    cudaFuncSetAttribute(qkv_mma_kernel,
                         cudaFuncAttributeMaxDynamicSharedMemorySize, SM_DYN);
    cudaFuncSetAttribute(proj_mma_kernel,
                         cudaFuncAttributeMaxDynamicSharedMemorySize, SM_DYN);

    prep_w_kernel<<<144, 256>>>(qkvw, pw);
    cpb_kernel<<<1, 256>>>(w1, b1, w2);
    qkv_mma_kernel<<<B / 2, 256, SM_DYN>>>(x, qb, vb);
    attn_kernel<<<dim3(B, HEADS), 256>>>(mask, ls);
    proj_mma_kernel<<<B / 2, 256, SM_DYN>>>(pb, out);
}